// round 2
// baseline (speedup 1.0000x reference)
#include <cuda_runtime.h>
#include <math_constants.h>
#include <cstdint>

// Problem geometry (fixed by the reference)
static constexpr int   B_DIM   = 64;
static constexpr int   FT      = 80 * 640;                 // 51200 elems per batch slice
static constexpr long long NTOT = (long long)B_DIM * FT;   // 3,276,800 elems per channel
static constexpr int   NWORDS  = (int)(NTOT / 32);         // 102,400 packed words
static constexpr float THR     = 20.0f;

// Strain peak bitmask scratch: bit i == "flat element i of strain is a peak".
// Every word is overwritten on every launch -> graph-replay deterministic.
__device__ unsigned g_strain_bits[NWORDS];

// Compute the 8-bit peak mask for 8 consecutive elements held in v0,v1 with
// scalar neighbors (left of v0.x, right of v1.w).
__device__ __forceinline__ unsigned peak_byte(float4 v0, float4 v1,
                                              float left, float right) {
    unsigned byte = 0;
    byte |= (v0.x >= THR && v0.x > left  && v0.x > v0.y) ?   1u : 0u;
    byte |= (v0.y >= THR && v0.y > v0.x && v0.y > v0.z) ?   2u : 0u;
    byte |= (v0.z >= THR && v0.z > v0.y && v0.z > v0.w) ?   4u : 0u;
    byte |= (v0.w >= THR && v0.w > v0.z && v0.w > v1.x) ?   8u : 0u;
    byte |= (v1.x >= THR && v1.x > v0.w && v1.x > v1.y) ?  16u : 0u;
    byte |= (v1.y >= THR && v1.y > v1.x && v1.y > v1.z) ?  32u : 0u;
    byte |= (v1.z >= THR && v1.z > v1.y && v1.z > v1.w) ?  64u : 0u;
    byte |= (v1.w >= THR && v1.w > v1.z && v1.w > right) ? 128u : 0u;
    return byte;
}

// ---------------------------------------------------------------------------
// Kernel 1: build the strain peak bitmask. 8 elements / thread (2x float4).
// Peak rule (channel-flat): x[i] >= 20 && x[i] > x[i-1] && x[i] > x[i+1].
// Global ends can never be peaks (handled via +inf sentinel neighbor).
// ---------------------------------------------------------------------------
__global__ void __launch_bounds__(256) strain_peaks_kernel(const float* __restrict__ x) {
    const unsigned FULL = 0xFFFFFFFFu;
    int tid  = threadIdx.x;
    int lane = tid & 31;
    long long g = (long long)blockIdx.x * 2048 + (long long)tid * 8;

    float4 v0 = *reinterpret_cast<const float4*>(x + g);
    float4 v1 = *reinterpret_cast<const float4*>(x + g + 4);

    float left  = __shfl_up_sync(FULL, v1.w, 1);   // prev lane's last element
    float right = __shfl_down_sync(FULL, v0.x, 1); // next lane's first element
    if (lane == 0)  left  = (g == 0)        ? CUDART_INF_F : __ldg(x + g - 1);
    if (lane == 31) right = (g + 8 >= NTOT) ? CUDART_INF_F : __ldg(x + g + 8);

    unsigned byte = peak_byte(v0, v1, left, right);

    // 4 lanes share one 32-bit word (8 bits each). OR-butterfly within the quad.
    unsigned word = byte << (8 * (lane & 3));
    word |= __shfl_xor_sync(FULL, word, 1);
    word |= __shfl_xor_sync(FULL, word, 2);
    if ((lane & 3) == 0) g_strain_bits[g >> 5] = word;
}

// ---------------------------------------------------------------------------
// Kernel 2: one block per (aux_channel n, batch b) pair. Streams the 51200-elem
// slice, computes aux peak bits, ANDs against the (L2-resident) strain bitmask,
// accumulating inter / c1 / c2 in a single pass. Then jaccard & ratio.
// ---------------------------------------------------------------------------
__global__ void __launch_bounds__(256) iou_kernel(const float* __restrict__ aux,
                                                  float* __restrict__ out,
                                                  int half) {
    const unsigned FULL = 0xFFFFFFFFu;
    int pair = blockIdx.x;          // n * 64 + b  (matches flat output order)
    int n    = pair >> 6;
    int b    = pair & 63;
    const float* qa = aux + (long long)n * NTOT;
    long long gbase = (long long)b * FT;

    int tid  = threadIdx.x;
    int lane = tid & 31;

    int inter = 0, c1 = 0, c2 = 0;

    // 51200 / (256 threads * 8 elems) = 25 iterations
    #pragma unroll 2
    for (int it = 0; it < FT / 2048; ++it) {
        long long g = gbase + (long long)it * 2048 + (long long)tid * 8;

        // Front-batch all memory: two LDG.128 + one strain word (L2-resident).
        float4  v0 = *reinterpret_cast<const float4*>(qa + g);
        float4  v1 = *reinterpret_cast<const float4*>(qa + g + 4);
        unsigned sw = g_strain_bits[g >> 5];           // 4 threads broadcast-share

        float left  = __shfl_up_sync(FULL, v1.w, 1);
        float right = __shfl_down_sync(FULL, v0.x, 1);
        if (lane == 0)  left  = (g == 0)        ? CUDART_INF_F : __ldg(qa + g - 1);
        if (lane == 31) right = (g + 8 >= NTOT) ? CUDART_INF_F : __ldg(qa + g + 8);

        unsigned byte  = peak_byte(v0, v1, left, right);
        unsigned sbyte = (sw >> (8 * (lane & 3))) & 0xFFu;
        inter += __popc(byte & sbyte);
        c1    += __popc(sbyte);                        // bytes partition the word: exact
        c2    += __popc(byte);
    }

    // Warp reduce
    #pragma unroll
    for (int off = 16; off; off >>= 1) {
        inter += __shfl_xor_sync(FULL, inter, off);
        c1    += __shfl_xor_sync(FULL, c1,    off);
        c2    += __shfl_xor_sync(FULL, c2,    off);
    }

    __shared__ int s_i[8], s_1[8], s_2[8];
    int w = tid >> 5;
    if (lane == 0) { s_i[w] = inter; s_1[w] = c1; s_2[w] = c2; }
    __syncthreads();

    if (tid == 0) {
        int I = 0, C1 = 0, C2 = 0;
        #pragma unroll
        for (int k = 0; k < 8; ++k) { I += s_i[k]; C1 += s_1[k]; C2 += s_2[k]; }
        float u = (float)(C1 + C2 - I);
        float jac, ratio;
        if (u == 0.0f) {               // inter==0 && union==0 -> both 1.0
            jac = 1.0f; ratio = 1.0f;
        } else {
            jac   = (float)I / u;
            ratio = (C1 == 0) ? 0.0f   // nan_to_num(0/0) -> 0; note I<=C1 so I==0 here
                              : (float)I / (float)C1;
        }
        out[pair]        = jac;        // iou half
        out[half + pair] = ratio;      // corr half
    }
}

extern "C" void kernel_launch(void* const* d_in, const int* in_sizes, int n_in,
                              void* d_out, int out_size) {
    const float* strain = (const float*)d_in[0];   // qt_strain [64,80,640]
    const float* aux    = (const float*)d_in[1];   // qt_aux [32,64,80,640]
    float* out          = (float*)d_out;           // [iou(2048) | corr(2048)]

    strain_peaks_kernel<<<(int)(NTOT / 2048), 256>>>(strain);
    iou_kernel<<<32 * B_DIM, 256>>>(aux, out, out_size / 2);
}